// round 5
// baseline (speedup 1.0000x reference)
#include <cuda_runtime.h>
#include <cuda_bf16.h>
#include <math.h>

// ---------------------------------------------------------------------------
// ann2_snn1 — bit-faithful emulation of the JAX/XLA-CPU reference (verified
// rel_err == 0.0). Numerics contract (must not change):
//  * every dot product: ONE f32 accumulator, strictly ascending k, __fmaf_rn
//    (zero-padded k-tails are exact: fma(0,0,acc)==acc)
//  * elementwise ops: separate f32 rounds in reference order
//  * logistic = 0.5 + 0.5*tanh(0.5x) with XLA's rational tanh
// ---------------------------------------------------------------------------

#define BATCH 1024
#define HID   500
#define NIN   784
#define NOUT  10
#define TLEN  100

__device__ float g_h[BATCH * HID];
__device__ float g_drive[BATCH * HID];

#define A1F ((float)1.1466802242428472)    // exp(-1/4)+exp(-1)
#define A2F ((float)-0.28650479686019009)  // -exp(-1/4)*exp(-1)
#define SGF ((float)0.77880078307140487)   // exp(-1/4)

__device__ __forceinline__ float xla_tanh_f32(float x)
{
    const float kMax = 7.90531110763549805f;
    float xc = fminf(fmaxf(x, -kMax), kMax);
    float x2 = __fmul_rn(xc, xc);
    float p = -2.76076847742355e-16f;
    p = __fadd_rn(__fmul_rn(p, x2), 2.00018790482477e-13f);
    p = __fadd_rn(__fmul_rn(p, x2), -8.60467152213735e-11f);
    p = __fadd_rn(__fmul_rn(p, x2), 5.12229709037114e-08f);
    p = __fadd_rn(__fmul_rn(p, x2), 1.48572235717979e-05f);
    p = __fadd_rn(__fmul_rn(p, x2), 6.37261928875436e-04f);
    p = __fadd_rn(__fmul_rn(p, x2), 4.89352455891786e-03f);
    float num = __fmul_rn(xc, p);
    float q = 1.19825839466702e-06f;
    q = __fadd_rn(__fmul_rn(q, x2), 1.18534705686654e-04f);
    q = __fadd_rn(__fmul_rn(q, x2), 2.26843463243900e-03f);
    q = __fadd_rn(__fmul_rn(q, x2), 4.89352518554385e-03f);
    float r = __fdiv_rn(num, q);
    return (fabsf(x) < 0.0004f) ? x : r;
}

__device__ __forceinline__ float xla_sigmoid(float x)
{
    float t = xla_tanh_f32(__fmul_rn(0.5f, x));
    return __fadd_rn(0.5f, __fmul_rn(0.5f, t));
}

// ---------------------------------------------------------------------------
// SGEMM: C[M,N] = act(A[M,K] @ W[N,K]^T + bias[N])
// BM=64, BN=32, BK=16, 64 threads, 8x4 micro-tile, register-prefetch double
// buffering. 48B smem per 32 lane-FMA (2x the intensity of 4x4).
// ---------------------------------------------------------------------------
#define BM 64
#define BN 32
#define BK 16
#define AS_LD 68
#define WS_LD 36

template<int ACT>
__global__ __launch_bounds__(64)
void gemm_bias_act(const float* __restrict__ A, const float* __restrict__ W,
                   const float* __restrict__ bias, float* __restrict__ C,
                   int M, int N, int K)
{
    __shared__ float As[2][BK][AS_LD];
    __shared__ float Ws[2][BK][WS_LD];

    const int tid = threadIdx.x;
    const int tx  = tid & 7;            // n dir: 8 x 4 = 32
    const int ty  = tid >> 3;           // m dir: 8 x 8 = 64
    const int bm  = blockIdx.y * BM;
    const int bn  = blockIdx.x * BN;

    // A loader: 4 passes over rows (ar, ar+16, ar+32, ar+48), one float4 each
    const int ar  = tid >> 2;           // 0..15
    const int ak4 = tid & 3;            // 0..3 -> k offset ak4*4
    // W loader: row wr (0..31), two float4 at k = wkh*8 + {0,4}
    const int wr  = tid & 31;
    const int wkh = tid >> 5;           // 0..1

    const int T = (K + BK - 1) / BK;

    float acc[8][4] = {};
    float4 pa[4], pw[2];

    auto loadA = [&](int kb) {
        int k = kb + ak4 * 4;
        #pragma unroll
        for (int p = 0; p < 4; p++) {
            const float* ap = A + (size_t)(bm + ar + p * 16) * K;
            float4 v;
            if (k + 3 < K) {
                v = *(const float4*)(ap + k);
            } else {
                v.x = (k + 0 < K) ? ap[k + 0] : 0.f;
                v.y = (k + 1 < K) ? ap[k + 1] : 0.f;
                v.z = (k + 2 < K) ? ap[k + 2] : 0.f;
                v.w = (k + 3 < K) ? ap[k + 3] : 0.f;
            }
            pa[p] = v;
        }
    };
    auto loadW = [&](int kb) {
        int row = bn + wr;
        #pragma unroll
        for (int f = 0; f < 2; f++) {
            int k = kb + wkh * 8 + f * 4;
            float4 v = make_float4(0.f, 0.f, 0.f, 0.f);
            if (row < N) {
                const float* wp = W + (size_t)row * K;
                if (k + 3 < K) {
                    v = *(const float4*)(wp + k);
                } else {
                    v.x = (k + 0 < K) ? wp[k + 0] : 0.f;
                    v.y = (k + 1 < K) ? wp[k + 1] : 0.f;
                    v.z = (k + 2 < K) ? wp[k + 2] : 0.f;
                    v.w = (k + 3 < K) ? wp[k + 3] : 0.f;
                }
            }
            pw[f] = v;
        }
    };
    auto stage = [&](int buf) {
        int ka = ak4 * 4;
        #pragma unroll
        for (int p = 0; p < 4; p++) {
            int row = ar + p * 16;
            As[buf][ka + 0][row] = pa[p].x;
            As[buf][ka + 1][row] = pa[p].y;
            As[buf][ka + 2][row] = pa[p].z;
            As[buf][ka + 3][row] = pa[p].w;
        }
        #pragma unroll
        for (int f = 0; f < 2; f++) {
            int kw = wkh * 8 + f * 4;
            Ws[buf][kw + 0][wr] = pw[f].x;
            Ws[buf][kw + 1][wr] = pw[f].y;
            Ws[buf][kw + 2][wr] = pw[f].z;
            Ws[buf][kw + 3][wr] = pw[f].w;
        }
    };

    loadA(0);
    loadW(0);
    stage(0);
    __syncthreads();

    for (int it = 0; it < T; it++) {
        const int cur = it & 1;
        if (it + 1 < T) {
            loadA((it + 1) * BK);
            loadW((it + 1) * BK);
        }
        #pragma unroll
        for (int k = 0; k < BK; k++) {
            float4 a0 = *(const float4*)&As[cur][k][ty * 8];
            float4 a1 = *(const float4*)&As[cur][k][ty * 8 + 4];
            float4 w4 = *(const float4*)&Ws[cur][k][tx * 4];
            float a[8] = {a0.x, a0.y, a0.z, a0.w, a1.x, a1.y, a1.z, a1.w};
            float w[4] = {w4.x, w4.y, w4.z, w4.w};
            #pragma unroll
            for (int i = 0; i < 8; i++)
                #pragma unroll
                for (int j = 0; j < 4; j++)
                    acc[i][j] = __fmaf_rn(a[i], w[j], acc[i][j]);
        }
        if (it + 1 < T) stage(cur ^ 1);
        __syncthreads();
    }

    // epilogue: bias + activation, float4 stores (N is a multiple of 4)
    const int n0 = bn + tx * 4;
    if (n0 < N) {
        float bv0 = bias[n0 + 0];
        float bv1 = bias[n0 + 1];
        float bv2 = bias[n0 + 2];
        float bv3 = bias[n0 + 3];
        #pragma unroll
        for (int i = 0; i < 8; i++) {
            int m = bm + ty * 8 + i;
            float x0 = __fadd_rn(acc[i][0], bv0);
            float x1 = __fadd_rn(acc[i][1], bv1);
            float x2 = __fadd_rn(acc[i][2], bv2);
            float x3 = __fadd_rn(acc[i][3], bv3);
            if (ACT == 0) {
                x0 = fmaxf(x0, 0.f); x1 = fmaxf(x1, 0.f);
                x2 = fmaxf(x2, 0.f); x3 = fmaxf(x3, 0.f);
            } else {
                x0 = xla_sigmoid(x0); x1 = xla_sigmoid(x1);
                x2 = xla_sigmoid(x2); x3 = xla_sigmoid(x3);
            }
            *(float4*)&C[(size_t)m * N + n0] = make_float4(x0, x1, x2, x3);
        }
    }
}

// ---------------------------------------------------------------------------
// Scan kernel: one block (256 threads) per batch element, psp chunked over t
// (44+44+12) so smem = 112 KB -> 2 blocks/SM (cross-block phase overlap).
//  phase1 (per chunk): 250 threads x 2 cols iterate psp (reference op order),
//    carries kept in registers across chunks.
//  phase2 (per chunk): thread = (t_local, j-pair); 2 sequential-k FMA chains
//    per thread reading psp rows (conflict-free) and w3 rows from smem.
//  phase3: 10 threads run the LIF recurrence (per-op f32 rounds).
// ---------------------------------------------------------------------------
#define CH 44

__global__ __launch_bounds__(256)
void scan_kernel(const float* __restrict__ w3, const float* __restrict__ b3,
                 float* __restrict__ out)
{
    extern __shared__ float sm[];
    float* sp = sm;                    // [CH][HID]    psp chunk (88,000 B)
    float* sw = sm + CH * HID;         // [NOUT][HID]  w3        (20,000 B)
    float* sc = sw + NOUT * HID;       // [TLEN][NOUT] dots      ( 4,000 B)

    const int b   = blockIdx.x;
    const int tid = threadIdx.x;

    // load w3 (coalesced float4)
    {
        const float4* src = (const float4*)w3;
        float4* dst = (float4*)sw;
        for (int i = tid; i < (NOUT * HID) / 4; i += 256) dst[i] = src[i];
    }

    float d0 = 0.f, d1 = 0.f;
    float p1a = 0.f, p2a = 0.f, p1b = 0.f, p2b = 0.f;
    if (tid < 250) {
        d0 = g_drive[(size_t)b * HID + tid];
        d1 = g_drive[(size_t)b * HID + tid + 250];
    }

    int t0 = 0;
    #pragma unroll
    for (int c = 0; c < 3; c++) {
        const int ch = (c < 2) ? CH : (TLEN - 2 * CH);   // 44,44,12
        __syncthreads();   // prev phase2 done (and w3 ready on c==0)

        // phase1: psp recurrence for this chunk
        if (tid < 250) {
            float* row = sp;
            for (int tl = 0; tl < ch; tl++, row += HID) {
                float pa = __fadd_rn(__fadd_rn(__fmul_rn(A1F, p1a),
                                               __fmul_rn(A2F, p2a)), d0);
                float pb = __fadd_rn(__fadd_rn(__fmul_rn(A1F, p1b),
                                               __fmul_rn(A2F, p2b)), d1);
                row[tid]       = pa;
                row[tid + 250] = pb;
                p2a = p1a; p1a = pa;
                p2b = p1b; p1b = pb;
            }
        }
        __syncthreads();

        // phase2: (t_local, j-pair) -> 2 ascending-k FMA chains
        if (tid < 5 * ch) {
            const int tl = tid / 5;
            const int j0 = (tid % 5) * 2;
            const float* pr = sp + tl * HID;
            const float* wa = sw + j0 * HID;
            const float* wb = wa + HID;
            float a0 = 0.f, a1 = 0.f;
            #pragma unroll 5
            for (int k = 0; k < HID; k += 4) {
                float4 pv = *(const float4*)(pr + k);
                float4 q0 = *(const float4*)(wa + k);
                float4 q1 = *(const float4*)(wb + k);
                a0 = __fmaf_rn(pv.x, q0.x, a0); a0 = __fmaf_rn(pv.y, q0.y, a0);
                a0 = __fmaf_rn(pv.z, q0.z, a0); a0 = __fmaf_rn(pv.w, q0.w, a0);
                a1 = __fmaf_rn(pv.x, q1.x, a1); a1 = __fmaf_rn(pv.y, q1.y, a1);
                a1 = __fmaf_rn(pv.z, q1.z, a1); a1 = __fmaf_rn(pv.w, q1.w, a1);
            }
            const int tg = t0 + tl;
            sc[tg * NOUT + j0]     = a0;
            sc[tg * NOUT + j0 + 1] = a1;
        }
        t0 += ch;
    }
    __syncthreads();

    // phase3: LIF recurrence (exact reference op order); spikes -> sp region
    if (tid < NOUT) {
        float bb = b3[tid];
        float v = 0.f, s = 0.f;
        float* spk = sp + tid * TLEN;
        for (int t = 0; t < TLEN; t++) {
            float cur = __fadd_rn(sc[t * NOUT + tid], bb);
            float t1  = __fmul_rn(SGF, v);
            float t2  = __fmul_rn(t1, __fsub_rn(1.f, s));
            float vn  = __fadd_rn(t2, cur);
            s = (vn >= 1.f) ? 1.f : 0.f;
            v = vn;
            spk[t] = s;
        }
    }
    __syncthreads();

    float* ob = out + (size_t)b * (NOUT * TLEN);
    for (int i = tid; i < NOUT * TLEN; i += 256) ob[i] = sp[i];
}

#define SCAN_SMEM ((CH * HID + NOUT * HID + TLEN * NOUT) * (int)sizeof(float))

extern "C" void kernel_launch(void* const* d_in, const int* in_sizes, int n_in,
                              void* d_out, int out_size)
{
    const float* inputs = (const float*)d_in[0];  // [1024, 784]
    const float* w1     = (const float*)d_in[1];  // [500, 784]
    const float* b1     = (const float*)d_in[2];  // [500]
    const float* w2     = (const float*)d_in[3];  // [500, 500]
    const float* b2     = (const float*)d_in[4];  // [500]
    const float* w3     = (const float*)d_in[5];  // [10, 500]
    const float* b3     = (const float*)d_in[6];  // [10]
    float* out          = (float*)d_out;          // [1024, 10, 100]

    float* h_buf;
    float* drive_buf;
    cudaGetSymbolAddress((void**)&h_buf, g_h);
    cudaGetSymbolAddress((void**)&drive_buf, g_drive);

    cudaFuncSetAttribute(scan_kernel,
                         cudaFuncAttributeMaxDynamicSharedMemorySize, SCAN_SMEM);

    dim3 blk(64);
    dim3 grd((HID + BN - 1) / BN, BATCH / BM);   // 16 x 16 = 256 blocks
    gemm_bias_act<0><<<grd, blk>>>(inputs, w1, b1, h_buf, BATCH, HID, NIN);
    gemm_bias_act<1><<<grd, blk>>>(h_buf, w2, b2, drive_buf, BATCH, HID, HID);
    scan_kernel<<<BATCH, 256, SCAN_SMEM>>>(w3, b3, out);
}

// round 6
// speedup vs baseline: 1.5384x; 1.5384x over previous
#include <cuda_runtime.h>
#include <cuda_bf16.h>
#include <math.h>

// ---------------------------------------------------------------------------
// ann2_snn1 — bit-faithful emulation of the JAX/XLA-CPU reference (verified
// rel_err == 0.0). Numerics contract (must not change):
//  * every dot product: ONE f32 accumulator, strictly ascending k, __fmaf_rn
//    (zero-padded k-tails are exact: fma(0,0,acc)==acc)
//  * elementwise ops: separate f32 rounds in reference order
//  * logistic = 0.5 + 0.5*tanh(0.5x) with XLA's rational tanh
// ---------------------------------------------------------------------------

#define BATCH 1024
#define HID   500
#define NIN   784
#define NOUT  10
#define TLEN  100

__device__ float g_h[BATCH * HID];
__device__ float g_drive[BATCH * HID];

#define A1F ((float)1.1466802242428472)    // exp(-1/4)+exp(-1)
#define A2F ((float)-0.28650479686019009)  // -exp(-1/4)*exp(-1)
#define SGF ((float)0.77880078307140487)   // exp(-1/4)

__device__ __forceinline__ float xla_tanh_f32(float x)
{
    const float kMax = 7.90531110763549805f;
    float xc = fminf(fmaxf(x, -kMax), kMax);
    float x2 = __fmul_rn(xc, xc);
    float p = -2.76076847742355e-16f;
    p = __fadd_rn(__fmul_rn(p, x2), 2.00018790482477e-13f);
    p = __fadd_rn(__fmul_rn(p, x2), -8.60467152213735e-11f);
    p = __fadd_rn(__fmul_rn(p, x2), 5.12229709037114e-08f);
    p = __fadd_rn(__fmul_rn(p, x2), 1.48572235717979e-05f);
    p = __fadd_rn(__fmul_rn(p, x2), 6.37261928875436e-04f);
    p = __fadd_rn(__fmul_rn(p, x2), 4.89352455891786e-03f);
    float num = __fmul_rn(xc, p);
    float q = 1.19825839466702e-06f;
    q = __fadd_rn(__fmul_rn(q, x2), 1.18534705686654e-04f);
    q = __fadd_rn(__fmul_rn(q, x2), 2.26843463243900e-03f);
    q = __fadd_rn(__fmul_rn(q, x2), 4.89352518554385e-03f);
    float r = __fdiv_rn(num, q);
    return (fabsf(x) < 0.0004f) ? x : r;
}

__device__ __forceinline__ float xla_sigmoid(float x)
{
    float t = xla_tanh_f32(__fmul_rn(0.5f, x));
    return __fadd_rn(0.5f, __fmul_rn(0.5f, t));
}

// ---------------------------------------------------------------------------
// Double-buffered SGEMM (R4 config — measured best): C = act(A@W^T + bias)
// BM=64, BN=32, BK=16, 128 threads, 4x4 micro-tile.
// ---------------------------------------------------------------------------
#define BM 64
#define BN 32
#define BK 16
#define AS_LD 68
#define WS_LD 36

template<int ACT>
__global__ __launch_bounds__(128)
void gemm_bias_act(const float* __restrict__ A, const float* __restrict__ W,
                   const float* __restrict__ bias, float* __restrict__ C,
                   int M, int N, int K)
{
    __shared__ float As[2][BK][AS_LD];
    __shared__ float Ws[2][BK][WS_LD];

    const int tid = threadIdx.x;
    const int tx  = tid & 7;
    const int ty  = tid >> 3;
    const int bm  = blockIdx.y * BM;
    const int bn  = blockIdx.x * BN;

    const int lrow = tid >> 1;
    const int lc   = tid & 1;
    const int wrow = tid >> 2;
    const int wk4  = tid & 3;

    const int T = (K + BK - 1) / BK;

    float acc[4][4] = {};
    float4 pa0, pa1, pw;

    auto loadA = [&](int kb, float4& r0, float4& r1) {
        const float* ap = A + (size_t)(bm + lrow) * K;
        int k0 = kb + lc * 8;
        #pragma unroll
        for (int f = 0; f < 2; f++) {
            int k = k0 + f * 4;
            float4 v;
            if (k + 3 < K) {
                v = *(const float4*)(ap + k);
            } else {
                v.x = (k + 0 < K) ? ap[k + 0] : 0.f;
                v.y = (k + 1 < K) ? ap[k + 1] : 0.f;
                v.z = (k + 2 < K) ? ap[k + 2] : 0.f;
                v.w = (k + 3 < K) ? ap[k + 3] : 0.f;
            }
            if (f == 0) r0 = v; else r1 = v;
        }
    };
    auto loadW = [&](int kb, float4& r) {
        int wr = bn + wrow;
        int k  = kb + wk4 * 4;
        float4 v = make_float4(0.f, 0.f, 0.f, 0.f);
        if (wr < N) {
            const float* wp = W + (size_t)wr * K;
            if (k + 3 < K) {
                v = *(const float4*)(wp + k);
            } else {
                v.x = (k + 0 < K) ? wp[k + 0] : 0.f;
                v.y = (k + 1 < K) ? wp[k + 1] : 0.f;
                v.z = (k + 2 < K) ? wp[k + 2] : 0.f;
                v.w = (k + 3 < K) ? wp[k + 3] : 0.f;
            }
        }
        r = v;
    };
    auto stage = [&](int buf, const float4& a0, const float4& a1, const float4& w) {
        int ka = lc * 8;
        As[buf][ka + 0][lrow] = a0.x;
        As[buf][ka + 1][lrow] = a0.y;
        As[buf][ka + 2][lrow] = a0.z;
        As[buf][ka + 3][lrow] = a0.w;
        As[buf][ka + 4][lrow] = a1.x;
        As[buf][ka + 5][lrow] = a1.y;
        As[buf][ka + 6][lrow] = a1.z;
        As[buf][ka + 7][lrow] = a1.w;
        int kw = wk4 * 4;
        Ws[buf][kw + 0][wrow] = w.x;
        Ws[buf][kw + 1][wrow] = w.y;
        Ws[buf][kw + 2][wrow] = w.z;
        Ws[buf][kw + 3][wrow] = w.w;
    };

    loadA(0, pa0, pa1);
    loadW(0, pw);
    stage(0, pa0, pa1, pw);
    __syncthreads();

    for (int it = 0; it < T; it++) {
        const int cur = it & 1;
        if (it + 1 < T) {
            loadA((it + 1) * BK, pa0, pa1);
            loadW((it + 1) * BK, pw);
        }
        #pragma unroll
        for (int k = 0; k < BK; k++) {
            float4 a4 = *(const float4*)&As[cur][k][ty * 4];
            float4 w4 = *(const float4*)&Ws[cur][k][tx * 4];
            float a[4] = {a4.x, a4.y, a4.z, a4.w};
            float w[4] = {w4.x, w4.y, w4.z, w4.w};
            #pragma unroll
            for (int i = 0; i < 4; i++)
                #pragma unroll
                for (int j = 0; j < 4; j++)
                    acc[i][j] = __fmaf_rn(a[i], w[j], acc[i][j]);
        }
        if (it + 1 < T) stage(cur ^ 1, pa0, pa1, pw);
        __syncthreads();
    }

    #pragma unroll
    for (int j = 0; j < 4; j++) {
        int n = bn + tx * 4 + j;
        if (n >= N) continue;
        float bv = bias[n];
        #pragma unroll
        for (int i = 0; i < 4; i++) {
            int m = bm + ty * 4 + i;
            float x = __fadd_rn(acc[i][j], bv);
            if (ACT == 0) x = fmaxf(x, 0.f);
            else          x = xla_sigmoid(x);
            C[(size_t)m * N + n] = x;
        }
    }
}

// ---------------------------------------------------------------------------
// Scan kernel: one block (256 threads) per batch element.
//  phase 1: 250 threads x 2 cols iterate psp (reference op order) -> smem.
//  phase 2: warp-aligned (t, j-group) layout:
//           warps 0-3: t = tid      (0..99 < TLEN), j = 0..4
//           warps 4-7: t = tid-128,                 j = 5..9
//           Each thread: 5 strict ascending-k FMA chains; psp row read ONCE
//           per (t,k) (stride-500 float4 -> conflict-free phases) and the 5
//           weight float4 loads are warp-uniform -> broadcast (free).
//           LDS traffic drops >10x vs (t, j-pair) layout.
//  phase 3: 10 threads run the LIF recurrence (per-op f32 rounds).
// ---------------------------------------------------------------------------
__global__ __launch_bounds__(256)
void scan_kernel(const float* __restrict__ w3, const float* __restrict__ b3,
                 float* __restrict__ out)
{
    extern __shared__ float sm[];
    float* sp = sm;                    // [TLEN][HID]  psp  (200,000 B)
    float* sw = sm + TLEN * HID;       // [NOUT][HID]  w3   ( 20,000 B)
    float* sc = sw + NOUT * HID;       // [TLEN][NOUT] dots (  4,000 B)

    const int b   = blockIdx.x;
    const int tid = threadIdx.x;

    // load w3 (coalesced float4)
    {
        const float4* src = (const float4*)w3;
        float4* dst = (float4*)sw;
        for (int i = tid; i < (NOUT * HID) / 4; i += 256) dst[i] = src[i];
    }

    // phase 1: psp recurrence, 2 columns per thread
    if (tid < 250) {
        const int k0 = tid, k1 = tid + 250;
        float d0 = g_drive[(size_t)b * HID + k0];
        float d1 = g_drive[(size_t)b * HID + k1];
        float p1a = 0.f, p2a = 0.f, p1b = 0.f, p2b = 0.f;
        #pragma unroll 4
        for (int t = 0; t < TLEN; t++) {
            float pa = __fadd_rn(__fadd_rn(__fmul_rn(A1F, p1a),
                                           __fmul_rn(A2F, p2a)), d0);
            float pb = __fadd_rn(__fadd_rn(__fmul_rn(A1F, p1b),
                                           __fmul_rn(A2F, p2b)), d1);
            sp[t * HID + k0] = pa;
            sp[t * HID + k1] = pb;
            p2a = p1a; p1a = pa;
            p2b = p1b; p1b = pb;
        }
    }
    __syncthreads();

    // phase 2: thread = t, 5 j-accumulators, warp-uniform j-group
    {
        const int jg = tid >> 7;           // 0 (warps 0-3) or 1 (warps 4-7)
        const int t  = tid & 127;
        if (t < TLEN) {
            const float* pr = sp + t * HID;
            const float* wb = sw + jg * 5 * HID;
            float a0 = 0.f, a1 = 0.f, a2 = 0.f, a3 = 0.f, a4 = 0.f;
            #pragma unroll 5
            for (int k = 0; k < HID; k += 4) {
                float4 pv = *(const float4*)(pr + k);
                float4 q0 = *(const float4*)(wb + 0 * HID + k);
                float4 q1 = *(const float4*)(wb + 1 * HID + k);
                float4 q2 = *(const float4*)(wb + 2 * HID + k);
                float4 q3 = *(const float4*)(wb + 3 * HID + k);
                float4 q4 = *(const float4*)(wb + 4 * HID + k);
                a0 = __fmaf_rn(pv.x, q0.x, a0); a0 = __fmaf_rn(pv.y, q0.y, a0);
                a0 = __fmaf_rn(pv.z, q0.z, a0); a0 = __fmaf_rn(pv.w, q0.w, a0);
                a1 = __fmaf_rn(pv.x, q1.x, a1); a1 = __fmaf_rn(pv.y, q1.y, a1);
                a1 = __fmaf_rn(pv.z, q1.z, a1); a1 = __fmaf_rn(pv.w, q1.w, a1);
                a2 = __fmaf_rn(pv.x, q2.x, a2); a2 = __fmaf_rn(pv.y, q2.y, a2);
                a2 = __fmaf_rn(pv.z, q2.z, a2); a2 = __fmaf_rn(pv.w, q2.w, a2);
                a3 = __fmaf_rn(pv.x, q3.x, a3); a3 = __fmaf_rn(pv.y, q3.y, a3);
                a3 = __fmaf_rn(pv.z, q3.z, a3); a3 = __fmaf_rn(pv.w, q3.w, a3);
                a4 = __fmaf_rn(pv.x, q4.x, a4); a4 = __fmaf_rn(pv.y, q4.y, a4);
                a4 = __fmaf_rn(pv.z, q4.z, a4); a4 = __fmaf_rn(pv.w, q4.w, a4);
            }
            float* scr = sc + t * NOUT + jg * 5;
            scr[0] = a0; scr[1] = a1; scr[2] = a2; scr[3] = a3; scr[4] = a4;
        }
    }
    __syncthreads();

    // phase 3: LIF recurrence (exact reference op order); spikes -> sp region
    if (tid < NOUT) {
        float bb = b3[tid];
        float v = 0.f, s = 0.f;
        float* spk = sp + tid * TLEN;
        for (int t = 0; t < TLEN; t++) {
            float cur = __fadd_rn(sc[t * NOUT + tid], bb);
            float t1  = __fmul_rn(SGF, v);
            float t2  = __fmul_rn(t1, __fsub_rn(1.f, s));
            float vn  = __fadd_rn(t2, cur);
            s = (vn >= 1.f) ? 1.f : 0.f;
            v = vn;
            spk[t] = s;
        }
    }
    __syncthreads();

    float* ob = out + (size_t)b * (NOUT * TLEN);
    for (int i = tid; i < NOUT * TLEN; i += 256) ob[i] = sp[i];
}

#define SCAN_SMEM ((TLEN * HID + NOUT * HID + TLEN * NOUT) * (int)sizeof(float))

extern "C" void kernel_launch(void* const* d_in, const int* in_sizes, int n_in,
                              void* d_out, int out_size)
{
    const float* inputs = (const float*)d_in[0];  // [1024, 784]
    const float* w1     = (const float*)d_in[1];  // [500, 784]
    const float* b1     = (const float*)d_in[2];  // [500]
    const float* w2     = (const float*)d_in[3];  // [500, 500]
    const float* b2     = (const float*)d_in[4];  // [500]
    const float* w3     = (const float*)d_in[5];  // [10, 500]
    const float* b3     = (const float*)d_in[6];  // [10]
    float* out          = (float*)d_out;          // [1024, 10, 100]

    float* h_buf;
    float* drive_buf;
    cudaGetSymbolAddress((void**)&h_buf, g_h);
    cudaGetSymbolAddress((void**)&drive_buf, g_drive);

    cudaFuncSetAttribute(scan_kernel,
                         cudaFuncAttributeMaxDynamicSharedMemorySize, SCAN_SMEM);

    dim3 blk(128);
    dim3 grd((HID + BN - 1) / BN, BATCH / BM);   // 16 x 16 = 256 blocks
    gemm_bias_act<0><<<grd, blk>>>(inputs, w1, b1, h_buf, BATCH, HID, NIN);
    gemm_bias_act<1><<<grd, blk>>>(h_buf, w2, b2, drive_buf, BATCH, HID, HID);
    scan_kernel<<<BATCH, 256, SCAN_SMEM>>>(w3, b3, out);
}